// round 12
// baseline (speedup 1.0000x reference)
#include <cuda_runtime.h>
#include <cuda_fp16.h>
#include <cstdint>

#define LATENT 128
#define DQ 32            // KQ_DIM
#define BATCH 8
#define NN 16384
#define KK 16
#define ROWS (BATCH * NN)            // 131072
#define BNK  (BATCH * NN * KK)       // 2097152

// combined projection table, fp16: row r has 64 halves = ks[0:32) | qs[32:64)
__device__ __align__(128) __half g_kq[ROWS * 64];
__device__ int g_idx_is64;

typedef unsigned u32;

__device__ __forceinline__ u32 smem_u32(const void* p) {
    u32 a;
    asm("{ .reg .u64 t; cvta.to.shared.u64 t, %1; cvt.u32.u64 %0, t; }"
        : "=r"(a) : "l"(p));
    return a;
}
__device__ __forceinline__ u32 cvt_bf16x2(float hi, float lo) {
    u32 r;
    asm("cvt.rn.bf16x2.f32 %0, %1, %2;" : "=r"(r) : "f"(hi), "f"(lo));
    return r;
}
__device__ __forceinline__ float bf16lo_f(u32 p) { return __uint_as_float(p << 16); }
__device__ __forceinline__ float bf16hi_f(u32 p) { return __uint_as_float(p & 0xffff0000u); }

__device__ __forceinline__ void mma_bf16(float* d,
                                         u32 a0, u32 a1, u32 a2, u32 a3,
                                         u32 b0, u32 b1) {
    asm volatile(
        "mma.sync.aligned.m16n8k16.row.col.f32.bf16.bf16.f32 "
        "{%0,%1,%2,%3}, {%4,%5,%6,%7}, {%8,%9}, {%0,%1,%2,%3};"
        : "+f"(d[0]), "+f"(d[1]), "+f"(d[2]), "+f"(d[3])
        : "r"(a0), "r"(a1), "r"(a2), "r"(a3), "r"(b0), "r"(b1));
}

__device__ __forceinline__ void cp_async16(u32 dst_smem, const void* src) {
    asm volatile("cp.async.cg.shared.global [%0], [%1], 16;"
                 :: "r"(dst_smem), "l"(src) : "memory");
}

// ---------------------------------------------------------------------------
// Phase 1 (bf16-split tensor GEMM, cp.async-staged A):
//   g_kq[row][n] = features[row].W[n] + b[n]  (n<32: ks, else qs), fp16 out.
// Per 128-thread block: 128 rows.
//   1) 4096 x cp.async.cg 16B stream the 128x128 fp32 feature tile into smem
//      (64.5 KB, rows padded to 132 floats) -- massive MLP, HBM-saturating.
//      Weight hi/lo bf16x2 conversion overlaps the fill.
//   2) MMA loop identical to round-11 but A fragments come from smem (LDS.64,
//      <=2-way conflicts), so no global latency in the loop.
// Split math: x = x_hi(bf16) + x_lo(bf16); D += AhBh + AlBh + AhBl.
// Block 0 / warp 0 detects index dtype (odd 32-bit words of small nonneg
// int64 are all zero; impossible for 256 genuine int32 indices).
// ---------------------------------------------------------------------------
#define WST 68     // shared stride (u32) for weight pair arrays
#define AST 132    // shared stride (floats) for A tile rows (16B-aligned, padded)

#define OFF_A    0
#define OFF_WHI  (128 * AST * 4)             // 67584
#define OFF_WLO  (OFF_WHI + 64 * WST * 4)    // +17408
#define OFF_BIAS (OFF_WLO + 64 * WST * 4)    // +17408
#define SM_TOTAL (OFF_BIAS + 64 * 4)         // 102656

template <bool DO_DETECT>
__global__ void __launch_bounds__(128)
proj_mma_kernel(const float* __restrict__ features,
                const float* __restrict__ ks_w, const float* __restrict__ ks_b,
                const float* __restrict__ qs_w, const float* __restrict__ qs_b,
                const int*   __restrict__ idx32)
{
    extern __shared__ __align__(16) char smem[];
    float* As      = reinterpret_cast<float*>(smem + OFF_A);
    u32*   whp_hi  = reinterpret_cast<u32*>(smem + OFF_WHI);
    u32*   whp_lo  = reinterpret_cast<u32*>(smem + OFF_WLO);
    float* bsh     = reinterpret_cast<float*>(smem + OFF_BIAS);
    const u32 sA   = smem_u32(As);

    int tid = threadIdx.x;

    if (DO_DETECT && blockIdx.x == 0 && tid < 32) {
        int all_hi_zero = 1;
        for (int i = tid; i < 256; i += 32)
            if (idx32[2 * i + 1] != 0) all_hi_zero = 0;
        all_hi_zero = __all_sync(0xffffffffu, all_hi_zero);
        if (tid == 0) g_idx_is64 = all_hi_zero;
    }

    int rb = blockIdx.x * 128;

    // ---- stage A tile via cp.async: 128 rows x 32 16B segments ----
    {
        const char* src = reinterpret_cast<const char*>(features + (size_t)rb * LATENT);
#pragma unroll 8
        for (int i = tid; i < 128 * 32; i += 128) {
            int row = i >> 5;
            int seg = i & 31;
            cp_async16(sA + (u32)(row * AST * 4 + seg * 16),
                       src + (size_t)row * 512 + seg * 16);
        }
        asm volatile("cp.async.commit_group;" ::: "memory");
    }

    // ---- weights hi/lo (overlaps the cp.async fill) ----
    for (int i = tid; i < 64 * 64; i += 128) {
        int n = i >> 6;                 // combined output 0..63
        int p = i & 63;                 // k-pair 0..63
        const float* src = (n < 32) ? (ks_w + n * LATENT) : (qs_w + (n - 32) * LATENT);
        float w0 = src[2 * p];
        float w1 = src[2 * p + 1];
        u32 hi = cvt_bf16x2(w1, w0);
        whp_hi[n * WST + p] = hi;
        whp_lo[n * WST + p] = cvt_bf16x2(w1 - bf16hi_f(hi), w0 - bf16lo_f(hi));
    }
    if (tid < 64)
        bsh[tid] = (tid < 32) ? ks_b[tid] : qs_b[tid - 32];

    asm volatile("cp.async.wait_group 0;" ::: "memory");
    __syncthreads();

    // ---- MMA main loop ----
    int warp = tid >> 5;
    int lane = tid & 31;
    int g    = lane >> 2;
    int tig  = lane & 3;

    float D[2][8][4];
#pragma unroll
    for (int nt = 0; nt < 8; nt++) {
        float b0 = bsh[nt * 8 + 2 * tig];
        float b1 = bsh[nt * 8 + 2 * tig + 1];
#pragma unroll
        for (int mt = 0; mt < 2; mt++) {
            D[mt][nt][0] = b0; D[mt][nt][1] = b1;
            D[mt][nt][2] = b0; D[mt][nt][3] = b1;
        }
    }

    // local A rows for this thread: warp*32 + mt*16 + {0,8} + g
    const float* ar[2];
    ar[0] = As + (warp * 32 + g) * AST;          // mt=0, +8*AST for row+8
    ar[1] = As + (warp * 32 + 16 + g) * AST;     // mt=1

#pragma unroll
    for (int ks = 0; ks < 8; ks++) {
        int k0 = ks * 16 + 2 * tig;

        u32 ah[2][4], al[2][4];
#pragma unroll
        for (int mt = 0; mt < 2; mt++) {
            float2 f[4];
            f[0] = *reinterpret_cast<const float2*>(ar[mt] + k0);
            f[1] = *reinterpret_cast<const float2*>(ar[mt] + 8 * AST + k0);
            f[2] = *reinterpret_cast<const float2*>(ar[mt] + k0 + 8);
            f[3] = *reinterpret_cast<const float2*>(ar[mt] + 8 * AST + k0 + 8);
#pragma unroll
            for (int r = 0; r < 4; r++) {
                u32 h = cvt_bf16x2(f[r].y, f[r].x);
                ah[mt][r] = h;
                al[mt][r] = cvt_bf16x2(f[r].y - bf16hi_f(h), f[r].x - bf16lo_f(h));
            }
        }

#pragma unroll
        for (int nt = 0; nt < 8; nt++) {
            int base = (nt * 8 + g) * WST + ks * 8 + tig;
            u32 b0h = whp_hi[base];
            u32 b1h = whp_hi[base + 4];
            u32 b0l = whp_lo[base];
            u32 b1l = whp_lo[base + 4];
#pragma unroll
            for (int mt = 0; mt < 2; mt++) {
                mma_bf16(D[mt][nt], ah[mt][0], ah[mt][1], ah[mt][2], ah[mt][3], b0h, b1h);
                mma_bf16(D[mt][nt], al[mt][0], al[mt][1], al[mt][2], al[mt][3], b0h, b1h);
                mma_bf16(D[mt][nt], ah[mt][0], ah[mt][1], ah[mt][2], ah[mt][3], b0l, b1l);
            }
        }
    }

    // ---- store fp16 combined table ----
#pragma unroll
    for (int mt = 0; mt < 2; mt++) {
        int row0 = rb + warp * 32 + mt * 16 + g;
#pragma unroll
        for (int nt = 0; nt < 8; nt++) {
            __half2 h01 = __floats2half2_rn(D[mt][nt][0], D[mt][nt][1]);
            __half2 h23 = __floats2half2_rn(D[mt][nt][2], D[mt][nt][3]);
            *reinterpret_cast<__half2*>(
                g_kq + (size_t)row0 * 64 + nt * 8 + 2 * tig) = h01;
            *reinterpret_cast<__half2*>(
                g_kq + (size_t)(row0 + 8) * 64 + nt * 8 + 2 * tig) = h23;
        }
    }
}

// ---------------------------------------------------------------------------
// Phase 2 (round-8 best-measured variant): out = (ks[x].qs[y]) * 32^-0.5.
// 4 lanes per logit (64B half-rows); each 4-lane group handles TWO adjacent
// logits (4 independent 16B gathers in flight per thread). 2x shfl_xor
// reduces within the group; lane 0 stores a float2.
// ---------------------------------------------------------------------------
__global__ void __launch_bounds__(256)
affinity_kernel(const void* __restrict__ indices_raw, float* __restrict__ out)
{
    int t   = blockIdx.x * 256 + threadIdx.x;
    int g   = t >> 2;                 // logit-pair id, < BNK/2
    int sub = t & 3;

    int lid0 = g << 1;
    int lid1 = lid0 | 1;
    int b    = lid0 >> 18;            // N*K = 2^18 (pair shares batch)

    long long x0, y0, x1, y1;
    if (g_idx_is64) {
        const long long* idx = (const long long*)indices_raw;
        x0 = idx[(size_t)BNK + lid0];
        x1 = idx[(size_t)BNK + lid1];
        y0 = idx[(size_t)2 * BNK + lid0];
        y1 = idx[(size_t)2 * BNK + lid1];
    } else {
        const int* idx = (const int*)indices_raw;
        x0 = idx[(size_t)BNK + lid0];
        x1 = idx[(size_t)BNK + lid1];
        y0 = idx[(size_t)2 * BNK + lid0];
        y1 = idx[(size_t)2 * BNK + lid1];
    }

    size_t base = (size_t)b << 14;
    const uint4* px0 = reinterpret_cast<const uint4*>(g_kq + ((base + (size_t)x0) << 6)) + sub;
    const uint4* py0 = reinterpret_cast<const uint4*>(g_kq + ((base + (size_t)y0) << 6) + 32) + sub;
    const uint4* px1 = reinterpret_cast<const uint4*>(g_kq + ((base + (size_t)x1) << 6)) + sub;
    const uint4* py1 = reinterpret_cast<const uint4*>(g_kq + ((base + (size_t)y1) << 6) + 32) + sub;

    uint4 ax0 = *px0;
    uint4 ay0 = *py0;
    uint4 ax1 = *px1;
    uint4 ay1 = *py1;

    const __half2* hx0 = reinterpret_cast<const __half2*>(&ax0);
    const __half2* hy0 = reinterpret_cast<const __half2*>(&ay0);
    const __half2* hx1 = reinterpret_cast<const __half2*>(&ax1);
    const __half2* hy1 = reinterpret_cast<const __half2*>(&ay1);

    float s0 = 0.0f, s1 = 0.0f;
#pragma unroll
    for (int i = 0; i < 4; i++) {
        float2 fx0 = __half22float2(hx0[i]);
        float2 fy0 = __half22float2(hy0[i]);
        float2 fx1 = __half22float2(hx1[i]);
        float2 fy1 = __half22float2(hy1[i]);
        s0 = fmaf(fx0.x, fy0.x, s0);
        s0 = fmaf(fx0.y, fy0.y, s0);
        s1 = fmaf(fx1.x, fy1.x, s1);
        s1 = fmaf(fx1.y, fy1.y, s1);
    }

#pragma unroll
    for (int m = 2; m >= 1; m >>= 1) {
        s0 += __shfl_xor_sync(0xffffffffu, s0, m);
        s1 += __shfl_xor_sync(0xffffffffu, s1, m);
    }

    if (sub == 0) {
        float2 o = make_float2(s0 * 0.17677669529663687f,
                               s1 * 0.17677669529663687f);  // 32^-0.5
        *reinterpret_cast<float2*>(out + lid0) = o;
    }
}

extern "C" void kernel_launch(void* const* d_in, const int* in_sizes, int n_in,
                              void* d_out, int out_size)
{
    const float* features = (const float*)d_in[0];
    const float* ks_w     = (const float*)d_in[1];
    const float* ks_b     = (const float*)d_in[2];
    const float* qs_w     = (const float*)d_in[3];
    const float* qs_b     = (const float*)d_in[4];
    const void*  indices  = d_in[5];
    float*       out      = (float*)d_out;

    cudaFuncSetAttribute(proj_mma_kernel<true>,
                         cudaFuncAttributeMaxDynamicSharedMemorySize, SM_TOTAL);
    // 128 threads = 4 warps x 32 rows = 128 rows per block
    proj_mma_kernel<true><<<ROWS / 128, 128, SM_TOTAL>>>(
        features, ks_w, ks_b, qs_w, qs_b, (const int*)indices);
    // 4 lanes x (BNK/2) logit-pairs
    affinity_kernel<<<(size_t)(BNK / 2) * 4 / 256, 256>>>(indices, out);
}

// round 13
// speedup vs baseline: 1.1925x; 1.1925x over previous
#include <cuda_runtime.h>
#include <cuda_fp16.h>
#include <cstdint>

#define LATENT 128
#define DQ 32            // KQ_DIM
#define BATCH 8
#define NN 16384
#define KK 16
#define ROWS (BATCH * NN)            // 131072
#define BNK  (BATCH * NN * KK)       // 2097152

// combined projection table, fp16: row r has 64 halves = ks[0:32) | qs[32:64)
__device__ __align__(128) __half g_kq[ROWS * 64];
__device__ int g_idx_is64;

typedef unsigned u32;

// pack two floats into f16x2 {hi, lo}
__device__ __forceinline__ u32 cvt_f16x2(float hi, float lo) {
    u32 r;
    asm("cvt.rn.f16x2.f32 %0, %1, %2;" : "=r"(r) : "f"(hi), "f"(lo));
    return r;
}

__device__ __forceinline__ void mma_f16(float* d,
                                        u32 a0, u32 a1, u32 a2, u32 a3,
                                        u32 b0, u32 b1) {
    asm volatile(
        "mma.sync.aligned.m16n8k16.row.col.f32.f16.f16.f32 "
        "{%0,%1,%2,%3}, {%4,%5,%6,%7}, {%8,%9}, {%0,%1,%2,%3};"
        : "+f"(d[0]), "+f"(d[1]), "+f"(d[2]), "+f"(d[3])
        : "r"(a0), "r"(a1), "r"(a2), "r"(a3), "r"(b0), "r"(b1));
}

// ---------------------------------------------------------------------------
// Phase 1 (single-pass fp16 tensor GEMM):
//   g_kq[row][n] = fp16( features[row].W[n] + b[n] )  (n<32: ks, else qs)
// fp16 inputs (11-bit mantissa) + f32 accumulate: element error ~2.4e-4 RMS,
// well inside the 1e-3 budget on top of the fp16 table storage error.
// This removes the bf16 hi/lo split arithmetic that was the proj issue-floor
// (3 instr/element -> 0.5) and cuts MMA count 3x.
// Each warp: 32 rows x 64 outputs (2 m-tiles x 8 n-tiles), 8 K-steps (K=16).
// m16n8k16 fragments (lane = g*4+tig):
//   A: a0={r g,k 2tig..+1} a1={r g+8} a2={r g,k+8} a3={r g+8,k+8}
//   B: b0={k 2tig..+1, n g} b1={k+8..}   [B = W^T]
//   D: c0={g,2tig} c1={g,2tig+1} c2={g+8,2tig} c3={g+8,2tig+1}
// Weights as f16x2 pairs in shared, stride 68 words (B LDS bank = 4g+tig,
// conflict-free). Block 0 / warp 0 detects index dtype (odd 32-bit words of
// small nonneg int64 are all zero; impossible for 256 genuine int32 indices).
// ---------------------------------------------------------------------------
#define WST 68   // shared stride in u32 for weight pair array

template <bool DO_DETECT>
__global__ void __launch_bounds__(128)
proj_mma_kernel(const float* __restrict__ features,
                const float* __restrict__ ks_w, const float* __restrict__ ks_b,
                const float* __restrict__ qs_w, const float* __restrict__ qs_b,
                const int*   __restrict__ idx32)
{
    if (DO_DETECT && blockIdx.x == 0 && threadIdx.x < 32) {
        int lane = threadIdx.x;
        int all_hi_zero = 1;
        for (int i = lane; i < 256; i += 32)
            if (idx32[2 * i + 1] != 0) all_hi_zero = 0;
        all_hi_zero = __all_sync(0xffffffffu, all_hi_zero);
        if (lane == 0) g_idx_is64 = all_hi_zero;
    }

    // whp[n][p]: f16x2 of W_combined[n][2p..2p+1]
    __shared__ u32 whp[64 * WST];
    __shared__ float bsh[64];

    for (int i = threadIdx.x; i < 64 * 64; i += 128) {
        int n = i >> 6;                 // combined output 0..63
        int p = i & 63;                 // k-pair 0..63
        const float* src = (n < 32) ? (ks_w + n * LATENT) : (qs_w + (n - 32) * LATENT);
        float w0 = src[2 * p];
        float w1 = src[2 * p + 1];
        whp[n * WST + p] = cvt_f16x2(w1, w0);
    }
    if (threadIdx.x < 32) {
        bsh[threadIdx.x]      = ks_b[threadIdx.x];
        bsh[threadIdx.x + 32] = qs_b[threadIdx.x];
    }
    __syncthreads();

    int warp = threadIdx.x >> 5;
    int lane = threadIdx.x & 31;
    int g    = lane >> 2;
    int tig  = lane & 3;

    int rb = (blockIdx.x * 4 + warp) * 32;     // this warp: rows rb..rb+31

    float D[2][8][4];
#pragma unroll
    for (int nt = 0; nt < 8; nt++) {
        float b0 = bsh[nt * 8 + 2 * tig];
        float b1 = bsh[nt * 8 + 2 * tig + 1];
#pragma unroll
        for (int mt = 0; mt < 2; mt++) {
            D[mt][nt][0] = b0; D[mt][nt][1] = b1;
            D[mt][nt][2] = b0; D[mt][nt][3] = b1;
        }
    }

    // A-row pointers: thread touches rows rb + {0,8,16,24} + g
    const float* rp[4];
    rp[0] = features + (size_t)(rb      + g) * LATENT;
    rp[1] = features + (size_t)(rb + 8  + g) * LATENT;
    rp[2] = features + (size_t)(rb + 16 + g) * LATENT;
    rp[3] = features + (size_t)(rb + 24 + g) * LATENT;

#pragma unroll
    for (int ks = 0; ks < 8; ks++) {
        int k0 = ks * 16 + 2 * tig;

        u32 a[2][4];
#pragma unroll
        for (int mt = 0; mt < 2; mt++) {
            float2 f0 = *reinterpret_cast<const float2*>(rp[2 * mt]     + k0);
            float2 f1 = *reinterpret_cast<const float2*>(rp[2 * mt + 1] + k0);
            float2 f2 = *reinterpret_cast<const float2*>(rp[2 * mt]     + k0 + 8);
            float2 f3 = *reinterpret_cast<const float2*>(rp[2 * mt + 1] + k0 + 8);
            a[mt][0] = cvt_f16x2(f0.y, f0.x);
            a[mt][1] = cvt_f16x2(f1.y, f1.x);
            a[mt][2] = cvt_f16x2(f2.y, f2.x);
            a[mt][3] = cvt_f16x2(f3.y, f3.x);
        }

#pragma unroll
        for (int nt = 0; nt < 8; nt++) {
            int base = (nt * 8 + g) * WST + ks * 8 + tig;
            u32 b0 = whp[base];
            u32 b1 = whp[base + 4];
#pragma unroll
            for (int mt = 0; mt < 2; mt++)
                mma_f16(D[mt][nt], a[mt][0], a[mt][1], a[mt][2], a[mt][3], b0, b1);
        }
    }

    // store fp16 into combined table
#pragma unroll
    for (int mt = 0; mt < 2; mt++) {
        int row0 = rb + mt * 16 + g;
#pragma unroll
        for (int nt = 0; nt < 8; nt++) {
            __half2 h01 = __floats2half2_rn(D[mt][nt][0], D[mt][nt][1]);
            __half2 h23 = __floats2half2_rn(D[mt][nt][2], D[mt][nt][3]);
            *reinterpret_cast<__half2*>(
                g_kq + (size_t)row0 * 64 + nt * 8 + 2 * tig) = h01;
            *reinterpret_cast<__half2*>(
                g_kq + (size_t)(row0 + 8) * 64 + nt * 8 + 2 * tig) = h23;
        }
    }
}

// ---------------------------------------------------------------------------
// Phase 2 (round-8 best-measured variant): out = (ks[x].qs[y]) * 32^-0.5.
// 4 lanes per logit (64B half-rows); each 4-lane group handles TWO adjacent
// logits (4 independent 16B gathers in flight per thread). 2x shfl_xor
// reduces within the group; lane 0 stores a float2.
// ---------------------------------------------------------------------------
__global__ void __launch_bounds__(256)
affinity_kernel(const void* __restrict__ indices_raw, float* __restrict__ out)
{
    int t   = blockIdx.x * 256 + threadIdx.x;
    int g   = t >> 2;                 // logit-pair id, < BNK/2
    int sub = t & 3;

    int lid0 = g << 1;
    int lid1 = lid0 | 1;
    int b    = lid0 >> 18;            // N*K = 2^18 (pair shares batch)

    long long x0, y0, x1, y1;
    if (g_idx_is64) {
        const long long* idx = (const long long*)indices_raw;
        x0 = idx[(size_t)BNK + lid0];
        x1 = idx[(size_t)BNK + lid1];
        y0 = idx[(size_t)2 * BNK + lid0];
        y1 = idx[(size_t)2 * BNK + lid1];
    } else {
        const int* idx = (const int*)indices_raw;
        x0 = idx[(size_t)BNK + lid0];
        x1 = idx[(size_t)BNK + lid1];
        y0 = idx[(size_t)2 * BNK + lid0];
        y1 = idx[(size_t)2 * BNK + lid1];
    }

    size_t base = (size_t)b << 14;
    const uint4* px0 = reinterpret_cast<const uint4*>(g_kq + ((base + (size_t)x0) << 6)) + sub;
    const uint4* py0 = reinterpret_cast<const uint4*>(g_kq + ((base + (size_t)y0) << 6) + 32) + sub;
    const uint4* px1 = reinterpret_cast<const uint4*>(g_kq + ((base + (size_t)x1) << 6)) + sub;
    const uint4* py1 = reinterpret_cast<const uint4*>(g_kq + ((base + (size_t)y1) << 6) + 32) + sub;

    uint4 ax0 = *px0;
    uint4 ay0 = *py0;
    uint4 ax1 = *px1;
    uint4 ay1 = *py1;

    const __half2* hx0 = reinterpret_cast<const __half2*>(&ax0);
    const __half2* hy0 = reinterpret_cast<const __half2*>(&ay0);
    const __half2* hx1 = reinterpret_cast<const __half2*>(&ax1);
    const __half2* hy1 = reinterpret_cast<const __half2*>(&ay1);

    float s0 = 0.0f, s1 = 0.0f;
#pragma unroll
    for (int i = 0; i < 4; i++) {
        float2 fx0 = __half22float2(hx0[i]);
        float2 fy0 = __half22float2(hy0[i]);
        float2 fx1 = __half22float2(hx1[i]);
        float2 fy1 = __half22float2(hy1[i]);
        s0 = fmaf(fx0.x, fy0.x, s0);
        s0 = fmaf(fx0.y, fy0.y, s0);
        s1 = fmaf(fx1.x, fy1.x, s1);
        s1 = fmaf(fx1.y, fy1.y, s1);
    }

#pragma unroll
    for (int m = 2; m >= 1; m >>= 1) {
        s0 += __shfl_xor_sync(0xffffffffu, s0, m);
        s1 += __shfl_xor_sync(0xffffffffu, s1, m);
    }

    if (sub == 0) {
        float2 o = make_float2(s0 * 0.17677669529663687f,
                               s1 * 0.17677669529663687f);  // 32^-0.5
        *reinterpret_cast<float2*>(out + lid0) = o;
    }
}

extern "C" void kernel_launch(void* const* d_in, const int* in_sizes, int n_in,
                              void* d_out, int out_size)
{
    const float* features = (const float*)d_in[0];
    const float* ks_w     = (const float*)d_in[1];
    const float* ks_b     = (const float*)d_in[2];
    const float* qs_w     = (const float*)d_in[3];
    const float* qs_b     = (const float*)d_in[4];
    const void*  indices  = d_in[5];
    float*       out      = (float*)d_out;

    // 128 threads = 4 warps x 32 rows = 128 rows per block
    proj_mma_kernel<true><<<ROWS / 128, 128>>>(features, ks_w, ks_b, qs_w, qs_b,
                                               (const int*)indices);
    // 4 lanes x (BNK/2) logit-pairs
    affinity_kernel<<<(size_t)(BNK / 2) * 4 / 256, 256>>>(indices, out);
}

// round 14
// speedup vs baseline: 1.2229x; 1.0255x over previous
#include <cuda_runtime.h>
#include <cuda_fp16.h>
#include <cstdint>

#define LATENT 128
#define DQ 32            // KQ_DIM
#define BATCH 8
#define NN 16384
#define KK 16
#define ROWS (BATCH * NN)            // 131072
#define BNK  (BATCH * NN * KK)       // 2097152

// combined projection table, fp16: row r has 64 halves = ks[0:32) | qs[32:64)
__device__ __align__(128) __half g_kq[ROWS * 64];
__device__ int g_idx_is64;

typedef unsigned u32;

// pack two floats into f16x2 {hi, lo}
__device__ __forceinline__ u32 cvt_f16x2(float hi, float lo) {
    u32 r;
    asm("cvt.rn.f16x2.f32 %0, %1, %2;" : "=r"(r) : "f"(hi), "f"(lo));
    return r;
}

__device__ __forceinline__ void mma_f16(float* d,
                                        u32 a0, u32 a1, u32 a2, u32 a3,
                                        u32 b0, u32 b1) {
    asm volatile(
        "mma.sync.aligned.m16n8k16.row.col.f32.f16.f16.f32 "
        "{%0,%1,%2,%3}, {%4,%5,%6,%7}, {%8,%9}, {%0,%1,%2,%3};"
        : "+f"(d[0]), "+f"(d[1]), "+f"(d[2]), "+f"(d[3])
        : "r"(a0), "r"(a1), "r"(a2), "r"(a3), "r"(b0), "r"(b1));
}

// ---------------------------------------------------------------------------
// Phase 1 (single-pass fp16 tensor GEMM, k-permuted fragments):
//   g_kq[row][n] = fp16( features[row].W[n] + b[n] )  (n<32: ks, else qs)
// The contraction over k is order-free, so we choose the k-ordering so that
// thread tig's A fragment is ONE contiguous float4 at k0 = ks*16 + 4*tig:
//   a0 = f16x2(x[k0],x[k0+1])    ("k first half" slot)
//   a2 = f16x2(x[k0+2],x[k0+3])  ("k+8" slot)
// and B smem stores the matching permuted weights at the SAME conflict-free
// addresses as before (bank = 4g+tig):
//   whp[n*WST + ks*8 + tig]     = f16x2(w[k0],w[k0+1])
//   whp[n*WST + ks*8 + tig + 4] = f16x2(w[k0+2],w[k0+3])
// Per k-step: 4x LDG.128 (was 8x LDG.64) + double-buffered prefetch of the
// next k-step, so load latency overlaps the previous MMA block.
// Each warp: 32 rows x 64 outputs (2 m-tiles x 8 n-tiles), 8 K-steps.
// Block 0 / warp 0 detects index dtype (odd 32-bit words of small nonneg
// int64 are all zero; impossible for 256 genuine int32 indices).
// ---------------------------------------------------------------------------
#define WST 68   // shared stride in u32 for weight pair array

template <bool DO_DETECT>
__global__ void __launch_bounds__(128)
proj_mma_kernel(const float* __restrict__ features,
                const float* __restrict__ ks_w, const float* __restrict__ ks_b,
                const float* __restrict__ qs_w, const float* __restrict__ qs_b,
                const int*   __restrict__ idx32)
{
    if (DO_DETECT && blockIdx.x == 0 && threadIdx.x < 32) {
        int lane = threadIdx.x;
        int all_hi_zero = 1;
        for (int i = lane; i < 256; i += 32)
            if (idx32[2 * i + 1] != 0) all_hi_zero = 0;
        all_hi_zero = __all_sync(0xffffffffu, all_hi_zero);
        if (lane == 0) g_idx_is64 = all_hi_zero;
    }

    __shared__ u32 whp[64 * WST];
    __shared__ float bsh[64];

    // permuted weight prologue: 64 outputs x 32 (ks,tig) quads
    for (int i = threadIdx.x; i < 64 * 32; i += 128) {
        int n  = i >> 5;
        int j  = i & 31;              // j = ks*4 + tig
        int ksx = j >> 2;
        int tg  = j & 3;
        int k0  = ksx * 16 + 4 * tg;
        const float* src = (n < 32) ? (ks_w + n * LATENT) : (qs_w + (n - 32) * LATENT);
        float4 w = *reinterpret_cast<const float4*>(src + k0);
        whp[n * WST + ksx * 8 + tg]     = cvt_f16x2(w.y, w.x);
        whp[n * WST + ksx * 8 + tg + 4] = cvt_f16x2(w.w, w.z);
    }
    if (threadIdx.x < 32) {
        bsh[threadIdx.x]      = ks_b[threadIdx.x];
        bsh[threadIdx.x + 32] = qs_b[threadIdx.x];
    }
    __syncthreads();

    int warp = threadIdx.x >> 5;
    int lane = threadIdx.x & 31;
    int g    = lane >> 2;
    int tig  = lane & 3;

    int rb = (blockIdx.x * 4 + warp) * 32;     // this warp: rows rb..rb+31

    float D[2][8][4];
#pragma unroll
    for (int nt = 0; nt < 8; nt++) {
        float b0 = bsh[nt * 8 + 2 * tig];
        float b1 = bsh[nt * 8 + 2 * tig + 1];
#pragma unroll
        for (int mt = 0; mt < 2; mt++) {
            D[mt][nt][0] = b0; D[mt][nt][1] = b1;
            D[mt][nt][2] = b0; D[mt][nt][3] = b1;
        }
    }

    // A-row pointers: thread touches rows rb + {0,8,16,24} + g
    const float* rp[4];
    rp[0] = features + (size_t)(rb      + g) * LATENT;
    rp[1] = features + (size_t)(rb + 8  + g) * LATENT;
    rp[2] = features + (size_t)(rb + 16 + g) * LATENT;
    rp[3] = features + (size_t)(rb + 24 + g) * LATENT;

    // double-buffered A: one float4 per fragment-row per k-step
    float4 fbuf[2][4];
    {
        int k0 = 4 * tig;
#pragma unroll
        for (int r = 0; r < 4; r++)
            fbuf[0][r] = *reinterpret_cast<const float4*>(rp[r] + k0);
    }

#pragma unroll
    for (int ks = 0; ks < 8; ks++) {
        int cur = ks & 1;
        if (ks < 7) {
            int k0 = (ks + 1) * 16 + 4 * tig;
#pragma unroll
            for (int r = 0; r < 4; r++)
                fbuf[cur ^ 1][r] = *reinterpret_cast<const float4*>(rp[r] + k0);
        }

        // a-fragments: rows (mt): r index 2mt (row+0), 2mt+1 (row+8)
        u32 a[2][4];
#pragma unroll
        for (int mt = 0; mt < 2; mt++) {
            float4 f0 = fbuf[cur][2 * mt];       // row g (+16mt)
            float4 f1 = fbuf[cur][2 * mt + 1];   // row g+8
            a[mt][0] = cvt_f16x2(f0.y, f0.x);
            a[mt][1] = cvt_f16x2(f1.y, f1.x);
            a[mt][2] = cvt_f16x2(f0.w, f0.z);
            a[mt][3] = cvt_f16x2(f1.w, f1.z);
        }

#pragma unroll
        for (int nt = 0; nt < 8; nt++) {
            int base = (nt * 8 + g) * WST + ks * 8 + tig;
            u32 b0 = whp[base];
            u32 b1 = whp[base + 4];
#pragma unroll
            for (int mt = 0; mt < 2; mt++)
                mma_f16(D[mt][nt], a[mt][0], a[mt][1], a[mt][2], a[mt][3], b0, b1);
        }
    }

    // store fp16 into combined table
#pragma unroll
    for (int mt = 0; mt < 2; mt++) {
        int row0 = rb + mt * 16 + g;
#pragma unroll
        for (int nt = 0; nt < 8; nt++) {
            __half2 h01 = __floats2half2_rn(D[mt][nt][0], D[mt][nt][1]);
            __half2 h23 = __floats2half2_rn(D[mt][nt][2], D[mt][nt][3]);
            *reinterpret_cast<__half2*>(
                g_kq + (size_t)row0 * 64 + nt * 8 + 2 * tig) = h01;
            *reinterpret_cast<__half2*>(
                g_kq + (size_t)(row0 + 8) * 64 + nt * 8 + 2 * tig) = h23;
        }
    }
}

// ---------------------------------------------------------------------------
// Phase 2 (round-8 best-measured variant): out = (ks[x].qs[y]) * 32^-0.5.
// 4 lanes per logit (64B half-rows); each 4-lane group handles TWO adjacent
// logits (4 independent 16B gathers in flight per thread). 2x shfl_xor
// reduces within the group; lane 0 stores a float2.
// ---------------------------------------------------------------------------
__global__ void __launch_bounds__(256)
affinity_kernel(const void* __restrict__ indices_raw, float* __restrict__ out)
{
    int t   = blockIdx.x * 256 + threadIdx.x;
    int g   = t >> 2;                 // logit-pair id, < BNK/2
    int sub = t & 3;

    int lid0 = g << 1;
    int lid1 = lid0 | 1;
    int b    = lid0 >> 18;            // N*K = 2^18 (pair shares batch)

    long long x0, y0, x1, y1;
    if (g_idx_is64) {
        const long long* idx = (const long long*)indices_raw;
        x0 = idx[(size_t)BNK + lid0];
        x1 = idx[(size_t)BNK + lid1];
        y0 = idx[(size_t)2 * BNK + lid0];
        y1 = idx[(size_t)2 * BNK + lid1];
    } else {
        const int* idx = (const int*)indices_raw;
        x0 = idx[(size_t)BNK + lid0];
        x1 = idx[(size_t)BNK + lid1];
        y0 = idx[(size_t)2 * BNK + lid0];
        y1 = idx[(size_t)2 * BNK + lid1];
    }

    size_t base = (size_t)b << 14;
    const uint4* px0 = reinterpret_cast<const uint4*>(g_kq + ((base + (size_t)x0) << 6)) + sub;
    const uint4* py0 = reinterpret_cast<const uint4*>(g_kq + ((base + (size_t)y0) << 6) + 32) + sub;
    const uint4* px1 = reinterpret_cast<const uint4*>(g_kq + ((base + (size_t)x1) << 6)) + sub;
    const uint4* py1 = reinterpret_cast<const uint4*>(g_kq + ((base + (size_t)y1) << 6) + 32) + sub;

    uint4 ax0 = *px0;
    uint4 ay0 = *py0;
    uint4 ax1 = *px1;
    uint4 ay1 = *py1;

    const __half2* hx0 = reinterpret_cast<const __half2*>(&ax0);
    const __half2* hy0 = reinterpret_cast<const __half2*>(&ay0);
    const __half2* hx1 = reinterpret_cast<const __half2*>(&ax1);
    const __half2* hy1 = reinterpret_cast<const __half2*>(&ay1);

    float s0 = 0.0f, s1 = 0.0f;
#pragma unroll
    for (int i = 0; i < 4; i++) {
        float2 fx0 = __half22float2(hx0[i]);
        float2 fy0 = __half22float2(hy0[i]);
        float2 fx1 = __half22float2(hx1[i]);
        float2 fy1 = __half22float2(hy1[i]);
        s0 = fmaf(fx0.x, fy0.x, s0);
        s0 = fmaf(fx0.y, fy0.y, s0);
        s1 = fmaf(fx1.x, fy1.x, s1);
        s1 = fmaf(fx1.y, fy1.y, s1);
    }

#pragma unroll
    for (int m = 2; m >= 1; m >>= 1) {
        s0 += __shfl_xor_sync(0xffffffffu, s0, m);
        s1 += __shfl_xor_sync(0xffffffffu, s1, m);
    }

    if (sub == 0) {
        float2 o = make_float2(s0 * 0.17677669529663687f,
                               s1 * 0.17677669529663687f);  // 32^-0.5
        *reinterpret_cast<float2*>(out + lid0) = o;
    }
}

extern "C" void kernel_launch(void* const* d_in, const int* in_sizes, int n_in,
                              void* d_out, int out_size)
{
    const float* features = (const float*)d_in[0];
    const float* ks_w     = (const float*)d_in[1];
    const float* ks_b     = (const float*)d_in[2];
    const float* qs_w     = (const float*)d_in[3];
    const float* qs_b     = (const float*)d_in[4];
    const void*  indices  = d_in[5];
    float*       out      = (float*)d_out;

    // 128 threads = 4 warps x 32 rows = 128 rows per block
    proj_mma_kernel<true><<<ROWS / 128, 128>>>(features, ks_w, ks_b, qs_w, qs_b,
                                               (const int*)indices);
    // 4 lanes x (BNK/2) logit-pairs
    affinity_kernel<<<(size_t)(BNK / 2) * 4 / 256, 256>>>(indices, out);
}

// round 15
// speedup vs baseline: 1.2870x; 1.0524x over previous
#include <cuda_runtime.h>
#include <cuda_fp16.h>
#include <cstdint>

#define LATENT 128
#define DQ 32            // KQ_DIM
#define BATCH 8
#define NN 16384
#define KK 16
#define ROWS (BATCH * NN)            // 131072
#define BNK  (BATCH * NN * KK)       // 2097152

// combined projection table, fp16: row r has 64 halves = ks[0:32) | qs[32:64)
__device__ __align__(128) __half g_kq[ROWS * 64];
__device__ int g_idx_is64;

typedef unsigned u32;

// pack two floats into f16x2 {hi, lo}
__device__ __forceinline__ u32 cvt_f16x2(float hi, float lo) {
    u32 r;
    asm("cvt.rn.f16x2.f32 %0, %1, %2;" : "=r"(r) : "f"(hi), "f"(lo));
    return r;
}

__device__ __forceinline__ void mma_f16(float* d,
                                        u32 a0, u32 a1, u32 a2, u32 a3,
                                        u32 b0, u32 b1) {
    asm volatile(
        "mma.sync.aligned.m16n8k16.row.col.f32.f16.f16.f32 "
        "{%0,%1,%2,%3}, {%4,%5,%6,%7}, {%8,%9}, {%0,%1,%2,%3};"
        : "+f"(d[0]), "+f"(d[1]), "+f"(d[2]), "+f"(d[3])
        : "r"(a0), "r"(a1), "r"(a2), "r"(a3), "r"(b0), "r"(b1));
}

// ---------------------------------------------------------------------------
// Phase 1 (single-pass fp16 tensor GEMM, k-permuted fragments, 256-thread
// blocks for in-flight-byte saturation):
//   g_kq[row][n] = fp16( features[row].W[n] + b[n] )  (n<32: ks, else qs)
// k-ordering chosen so thread tig's A fragment is ONE contiguous float4 at
// k0 = ks*16 + 4*tig; B smem stores matching permuted weights at conflict-
// free addresses (bank = 4g+tig). Depth-2 prefetch (k+2) keeps 8 float4 per
// thread in flight; 8 warps x 32 rows = 256 rows per block halves the wave
// count and amortizes the weight prologue over 2x rows.
// Block 0 / warp 0 detects index dtype (odd 32-bit words of small nonneg
// int64 are all zero; impossible for 256 genuine int32 indices).
// ---------------------------------------------------------------------------
#define WST 68   // shared stride in u32 for weight pair array

template <bool DO_DETECT>
__global__ void __launch_bounds__(256)
proj_mma_kernel(const float* __restrict__ features,
                const float* __restrict__ ks_w, const float* __restrict__ ks_b,
                const float* __restrict__ qs_w, const float* __restrict__ qs_b,
                const int*   __restrict__ idx32)
{
    if (DO_DETECT && blockIdx.x == 0 && threadIdx.x < 32) {
        int lane = threadIdx.x;
        int all_hi_zero = 1;
        for (int i = lane; i < 256; i += 32)
            if (idx32[2 * i + 1] != 0) all_hi_zero = 0;
        all_hi_zero = __all_sync(0xffffffffu, all_hi_zero);
        if (lane == 0) g_idx_is64 = all_hi_zero;
    }

    __shared__ u32 whp[64 * WST];
    __shared__ float bsh[64];

    // permuted weight prologue: 64 outputs x 32 (ks,tig) quads
    for (int i = threadIdx.x; i < 64 * 32; i += 256) {
        int n  = i >> 5;
        int j  = i & 31;              // j = ks*4 + tig
        int ksx = j >> 2;
        int tg  = j & 3;
        int k0  = ksx * 16 + 4 * tg;
        const float* src = (n < 32) ? (ks_w + n * LATENT) : (qs_w + (n - 32) * LATENT);
        float4 w = *reinterpret_cast<const float4*>(src + k0);
        whp[n * WST + ksx * 8 + tg]     = cvt_f16x2(w.y, w.x);
        whp[n * WST + ksx * 8 + tg + 4] = cvt_f16x2(w.w, w.z);
    }
    if (threadIdx.x < 32) {
        bsh[threadIdx.x]      = ks_b[threadIdx.x];
        bsh[threadIdx.x + 32] = qs_b[threadIdx.x];
    }
    __syncthreads();

    int warp = threadIdx.x >> 5;       // 0..7
    int lane = threadIdx.x & 31;
    int g    = lane >> 2;
    int tig  = lane & 3;

    int rb = (blockIdx.x * 8 + warp) * 32;     // this warp: rows rb..rb+31

    float D[2][8][4];
#pragma unroll
    for (int nt = 0; nt < 8; nt++) {
        float b0 = bsh[nt * 8 + 2 * tig];
        float b1 = bsh[nt * 8 + 2 * tig + 1];
#pragma unroll
        for (int mt = 0; mt < 2; mt++) {
            D[mt][nt][0] = b0; D[mt][nt][1] = b1;
            D[mt][nt][2] = b0; D[mt][nt][3] = b1;
        }
    }

    // A-row pointers: thread touches rows rb + {0,8,16,24} + g
    const float* rp[4];
    rp[0] = features + (size_t)(rb      + g) * LATENT;
    rp[1] = features + (size_t)(rb + 8  + g) * LATENT;
    rp[2] = features + (size_t)(rb + 16 + g) * LATENT;
    rp[3] = features + (size_t)(rb + 24 + g) * LATENT;

    // depth-2 prefetch: fbuf[p] holds k-step (ks with ks&1==p)
    float4 fbuf[2][4];
    {
        int k0a = 4 * tig;
        int k0b = 16 + 4 * tig;
#pragma unroll
        for (int r = 0; r < 4; r++) {
            fbuf[0][r] = *reinterpret_cast<const float4*>(rp[r] + k0a);
            fbuf[1][r] = *reinterpret_cast<const float4*>(rp[r] + k0b);
        }
    }

#pragma unroll
    for (int ks = 0; ks < 8; ks++) {
        int cur = ks & 1;

        // consume buffer into a-fragments (frees fbuf[cur])
        u32 a[2][4];
#pragma unroll
        for (int mt = 0; mt < 2; mt++) {
            float4 f0 = fbuf[cur][2 * mt];       // row g (+16mt)
            float4 f1 = fbuf[cur][2 * mt + 1];   // row g+8
            a[mt][0] = cvt_f16x2(f0.y, f0.x);
            a[mt][1] = cvt_f16x2(f1.y, f1.x);
            a[mt][2] = cvt_f16x2(f0.w, f0.z);
            a[mt][3] = cvt_f16x2(f1.w, f1.z);
        }

        // prefetch k-step ks+2 into the freed slot
        if (ks < 6) {
            int k0 = (ks + 2) * 16 + 4 * tig;
#pragma unroll
            for (int r = 0; r < 4; r++)
                fbuf[cur][r] = *reinterpret_cast<const float4*>(rp[r] + k0);
        }

#pragma unroll
        for (int nt = 0; nt < 8; nt++) {
            int base = (nt * 8 + g) * WST + ks * 8 + tig;
            u32 b0 = whp[base];
            u32 b1 = whp[base + 4];
#pragma unroll
            for (int mt = 0; mt < 2; mt++)
                mma_f16(D[mt][nt], a[mt][0], a[mt][1], a[mt][2], a[mt][3], b0, b1);
        }
    }

    // store fp16 into combined table
#pragma unroll
    for (int mt = 0; mt < 2; mt++) {
        int row0 = rb + mt * 16 + g;
#pragma unroll
        for (int nt = 0; nt < 8; nt++) {
            __half2 h01 = __floats2half2_rn(D[mt][nt][0], D[mt][nt][1]);
            __half2 h23 = __floats2half2_rn(D[mt][nt][2], D[mt][nt][3]);
            *reinterpret_cast<__half2*>(
                g_kq + (size_t)row0 * 64 + nt * 8 + 2 * tig) = h01;
            *reinterpret_cast<__half2*>(
                g_kq + (size_t)(row0 + 8) * 64 + nt * 8 + 2 * tig) = h23;
        }
    }
}

// ---------------------------------------------------------------------------
// Phase 2 (round-8 best-measured variant): out = (ks[x].qs[y]) * 32^-0.5.
// 4 lanes per logit (64B half-rows); each 4-lane group handles TWO adjacent
// logits (4 independent 16B gathers in flight per thread). 2x shfl_xor
// reduces within the group; lane 0 stores a float2.
// ---------------------------------------------------------------------------
__global__ void __launch_bounds__(256)
affinity_kernel(const void* __restrict__ indices_raw, float* __restrict__ out)
{
    int t   = blockIdx.x * 256 + threadIdx.x;
    int g   = t >> 2;                 // logit-pair id, < BNK/2
    int sub = t & 3;

    int lid0 = g << 1;
    int lid1 = lid0 | 1;
    int b    = lid0 >> 18;            // N*K = 2^18 (pair shares batch)

    long long x0, y0, x1, y1;
    if (g_idx_is64) {
        const long long* idx = (const long long*)indices_raw;
        x0 = idx[(size_t)BNK + lid0];
        x1 = idx[(size_t)BNK + lid1];
        y0 = idx[(size_t)2 * BNK + lid0];
        y1 = idx[(size_t)2 * BNK + lid1];
    } else {
        const int* idx = (const int*)indices_raw;
        x0 = idx[(size_t)BNK + lid0];
        x1 = idx[(size_t)BNK + lid1];
        y0 = idx[(size_t)2 * BNK + lid0];
        y1 = idx[(size_t)2 * BNK + lid1];
    }

    size_t base = (size_t)b << 14;
    const uint4* px0 = reinterpret_cast<const uint4*>(g_kq + ((base + (size_t)x0) << 6)) + sub;
    const uint4* py0 = reinterpret_cast<const uint4*>(g_kq + ((base + (size_t)y0) << 6) + 32) + sub;
    const uint4* px1 = reinterpret_cast<const uint4*>(g_kq + ((base + (size_t)x1) << 6)) + sub;
    const uint4* py1 = reinterpret_cast<const uint4*>(g_kq + ((base + (size_t)y1) << 6) + 32) + sub;

    uint4 ax0 = *px0;
    uint4 ay0 = *py0;
    uint4 ax1 = *px1;
    uint4 ay1 = *py1;

    const __half2* hx0 = reinterpret_cast<const __half2*>(&ax0);
    const __half2* hy0 = reinterpret_cast<const __half2*>(&ay0);
    const __half2* hx1 = reinterpret_cast<const __half2*>(&ax1);
    const __half2* hy1 = reinterpret_cast<const __half2*>(&ay1);

    float s0 = 0.0f, s1 = 0.0f;
#pragma unroll
    for (int i = 0; i < 4; i++) {
        float2 fx0 = __half22float2(hx0[i]);
        float2 fy0 = __half22float2(hy0[i]);
        float2 fx1 = __half22float2(hx1[i]);
        float2 fy1 = __half22float2(hy1[i]);
        s0 = fmaf(fx0.x, fy0.x, s0);
        s0 = fmaf(fx0.y, fy0.y, s0);
        s1 = fmaf(fx1.x, fy1.x, s1);
        s1 = fmaf(fx1.y, fy1.y, s1);
    }

#pragma unroll
    for (int m = 2; m >= 1; m >>= 1) {
        s0 += __shfl_xor_sync(0xffffffffu, s0, m);
        s1 += __shfl_xor_sync(0xffffffffu, s1, m);
    }

    if (sub == 0) {
        float2 o = make_float2(s0 * 0.17677669529663687f,
                               s1 * 0.17677669529663687f);  // 32^-0.5
        *reinterpret_cast<float2*>(out + lid0) = o;
    }
}

extern "C" void kernel_launch(void* const* d_in, const int* in_sizes, int n_in,
                              void* d_out, int out_size)
{
    const float* features = (const float*)d_in[0];
    const float* ks_w     = (const float*)d_in[1];
    const float* ks_b     = (const float*)d_in[2];
    const float* qs_w     = (const float*)d_in[3];
    const float* qs_b     = (const float*)d_in[4];
    const void*  indices  = d_in[5];
    float*       out      = (float*)d_out;

    // 256 threads = 8 warps x 32 rows = 256 rows per block
    proj_mma_kernel<true><<<ROWS / 256, 256>>>(features, ks_w, ks_b, qs_w, qs_b,
                                               (const int*)indices);
    // 4 lanes x (BNK/2) logit-pairs
    affinity_kernel<<<(size_t)(BNK / 2) * 4 / 256, 256>>>(indices, out);
}